// round 17
// baseline (speedup 1.0000x reference)
#include <cuda_runtime.h>
#include <cuda_fp16.h>
#include <cstdint>

// Problem constants
#define B_   4
#define S_   2048
#define D_   1024
#define H_   16
#define HD_  64
#define BH_  (B_ * H_)          // 64

// Scratch (allocation-free rule: __device__ globals)
__device__ float g_Q[B_ * S_ * D_];
__device__ float g_K[B_ * S_ * D_];
__device__ float g_V[B_ * S_ * D_];
__device__ float g_X[B_ * S_ * D_];
__device__ float g_inv[(size_t)BH_ * S_];     // 1/rowsum per (bh, q)

// ============================================================================
// PTX helpers — baseline ISA only (ldmatrix sm_75+, mma.sync sm_80+).
// ============================================================================
__device__ __forceinline__ uint32_t smem_u32(const void* p) {
    uint32_t a;
    asm("{ .reg .u64 t; cvta.to.shared.u64 t, %1; cvt.u32.u64 %0, t; }"
        : "=r"(a) : "l"(p));
    return a;
}

__device__ __forceinline__ void ldmat_x4(uint32_t* r, uint32_t addr) {
    asm volatile("ldmatrix.sync.aligned.m8n8.x4.shared.b16 {%0,%1,%2,%3}, [%4];"
        : "=r"(r[0]), "=r"(r[1]), "=r"(r[2]), "=r"(r[3]) : "r"(addr));
}
__device__ __forceinline__ void ldmat_x2(uint32_t* r, uint32_t addr) {
    asm volatile("ldmatrix.sync.aligned.m8n8.x2.shared.b16 {%0,%1}, [%2];"
        : "=r"(r[0]), "=r"(r[1]) : "r"(addr));
}
__device__ __forceinline__ void ldmat_x2_trans(uint32_t* r, uint32_t addr) {
    asm volatile("ldmatrix.sync.aligned.m8n8.x2.trans.shared.b16 {%0,%1}, [%2];"
        : "=r"(r[0]), "=r"(r[1]) : "r"(addr));
}
// D += A * B, m16n8k16, fp16 in, fp32 accumulate
__device__ __forceinline__ void mma16816(float* d, const uint32_t* a,
                                         const uint32_t* b) {
    asm volatile("mma.sync.aligned.m16n8k16.row.col.f32.f16.f16.f32 "
        "{%0,%1,%2,%3}, {%4,%5,%6,%7}, {%8,%9}, {%0,%1,%2,%3};"
        : "+f"(d[0]), "+f"(d[1]), "+f"(d[2]), "+f"(d[3])
        : "r"(a[0]), "r"(a[1]), "r"(a[2]), "r"(a[3]), "r"(b[0]), "r"(b[1]));
}

__device__ __forceinline__ uint32_t pack2(__half a, __half b) {
    __half2 h = __halves2half2(a, b);
    return *reinterpret_cast<uint32_t*>(&h);
}

// split one float4 into hi/lo fp16x2 pairs
__device__ __forceinline__ void split4(float4 v, uint2& hi, uint2& lo) {
    __half h0 = __float2half_rn(v.x), h1 = __float2half_rn(v.y);
    __half h2 = __float2half_rn(v.z), h3 = __float2half_rn(v.w);
    __half l0 = __float2half_rn(v.x - __half2float(h0));
    __half l1 = __float2half_rn(v.y - __half2float(h1));
    __half l2 = __float2half_rn(v.z - __half2float(h2));
    __half l3 = __float2half_rn(v.w - __half2float(h3));
    hi = make_uint2(pack2(h0, h1), pack2(h2, h3));
    lo = make_uint2(pack2(l0, l1), pack2(l2, l3));
}

// split one float2 into hi/lo fp16x2 words
__device__ __forceinline__ void split2(float2 v, uint32_t& hi, uint32_t& lo) {
    __half h0 = __float2half_rn(v.x), h1 = __float2half_rn(v.y);
    __half l0 = __float2half_rn(v.x - __half2float(h0));
    __half l1 = __float2half_rn(v.y - __half2float(h1));
    hi = pack2(h0, h1);
    lo = pack2(l0, l1);
}

// ============================================================================
// Projection GEMM (unchanged — proven): mma.sync fp16x3
// C[m,n] = sum_k A[m,k] * W[n,k] + bias[n]    (M=8192, N=1024, K=1024)
// ============================================================================
#define AH_OFF 0
#define AL_OFF 10240
#define WH_OFF 20480
#define WL_OFF 30720
#define PBUF   40960
#define PROJ_SMEM (2 * PBUF)     // 81920 bytes

__global__ __launch_bounds__(256, 1)
void proj_mma_kernel(const float* __restrict__ A, const float* __restrict__ W,
                     const float* __restrict__ bias, float* __restrict__ C)
{
    extern __shared__ __align__(16) char smem[];
    const uint32_t sb = smem_u32(smem);

    const int tid  = threadIdx.x;
    const int wid  = tid >> 5;
    const int lane = tid & 31;
    const int m0   = blockIdx.y * 128;
    const int n0   = blockIdx.x * 128;
    const int wm   = wid >> 2;
    const int wn   = wid & 3;

    const float* Ab = A + (size_t)m0 * D_;
    const float* Wb = W + (size_t)n0 * D_;

    int frow[4], fc4[4];
    #pragma unroll
    for (int i = 0; i < 4; i++) {
        int idx = tid + i * 256;
        frow[i] = idx >> 3;
        fc4[i]  = idx & 7;
    }

    const uint32_t aBase = sb +
        (uint32_t)(((wm * 64 + (lane & 15)) * 40 + (lane >> 4) * 8) * 2);
    const uint32_t bBase = sb +
        (uint32_t)(((wn * 32 + (lane & 7)) * 40 + ((lane >> 3) & 1) * 8) * 2);

    float acc[4][4][4] = {};

    float4 va[4], vw[4];
    #pragma unroll
    for (int i = 0; i < 4; i++) {
        va[i] = __ldg((const float4*)(Ab + (size_t)frow[i] * D_ + fc4[i] * 4));
        vw[i] = __ldg((const float4*)(Wb + (size_t)frow[i] * D_ + fc4[i] * 4));
    }

    for (int it = 0; it < 32; it++) {
        const int buf = it & 1;
        char* bp = smem + buf * PBUF;

        #pragma unroll
        for (int i = 0; i < 4; i++) {
            const uint32_t off = (uint32_t)(frow[i] * 80 + fc4[i] * 8);
            uint2 hi, lo;
            split4(va[i], hi, lo);
            *reinterpret_cast<uint2*>(bp + AH_OFF + off) = hi;
            *reinterpret_cast<uint2*>(bp + AL_OFF + off) = lo;
            split4(vw[i], hi, lo);
            *reinterpret_cast<uint2*>(bp + WH_OFF + off) = hi;
            *reinterpret_cast<uint2*>(bp + WL_OFF + off) = lo;
        }
        __syncthreads();

        if (it < 31) {
            const int kt = (it + 1) * 32;
            #pragma unroll
            for (int i = 0; i < 4; i++) {
                va[i] = __ldg((const float4*)(Ab + (size_t)frow[i] * D_ + kt + fc4[i] * 4));
                vw[i] = __ldg((const float4*)(Wb + (size_t)frow[i] * D_ + kt + fc4[i] * 4));
            }
        }

        const uint32_t bo = (uint32_t)(buf * PBUF);
        #pragma unroll
        for (int ks = 0; ks < 2; ks++) {
            uint32_t ah[4][4], al[4][4], wh[4][2], wl[4][2];
            #pragma unroll
            for (int mf = 0; mf < 4; mf++) {
                ldmat_x4(ah[mf], aBase + bo + AH_OFF + mf * 1280 + ks * 32);
                ldmat_x4(al[mf], aBase + bo + AL_OFF + mf * 1280 + ks * 32);
            }
            #pragma unroll
            for (int nf = 0; nf < 4; nf++) {
                ldmat_x2(wh[nf], bBase + bo + WH_OFF + nf * 640 + ks * 32);
                ldmat_x2(wl[nf], bBase + bo + WL_OFF + nf * 640 + ks * 32);
            }
            #pragma unroll
            for (int mf = 0; mf < 4; mf++) {
                #pragma unroll
                for (int nf = 0; nf < 4; nf++) {
                    mma16816(acc[mf][nf], ah[mf], wh[nf]);
                    mma16816(acc[mf][nf], ah[mf], wl[nf]);
                    mma16816(acc[mf][nf], al[mf], wh[nf]);
                }
            }
        }
        __syncthreads();
    }

    const int r0 = m0 + wm * 64 + (lane >> 2);
    #pragma unroll
    for (int mf = 0; mf < 4; mf++) {
        #pragma unroll
        for (int nf = 0; nf < 4; nf++) {
            const int c = n0 + wn * 32 + nf * 8 + (lane & 3) * 2;
            const float2 bv = *reinterpret_cast<const float2*>(bias + c);
            float* p0 = C + (size_t)(r0 + mf * 16) * D_ + c;
            float* p1 = C + (size_t)(r0 + mf * 16 + 8) * D_ + c;
            *reinterpret_cast<float2*>(p0) =
                make_float2(acc[mf][nf][0] + bv.x, acc[mf][nf][1] + bv.y);
            *reinterpret_cast<float2*>(p1) =
                make_float2(acc[mf][nf][2] + bv.x, acc[mf][nf][3] + bv.y);
        }
    }
}

// ============================================================================
// scores2: one CTA per (bh, 128q rows), loops ALL 16 k-tiles.
// Q split once -> register-resident A-frags. K double-buffered, reg-prefetched.
// Warp = 16q x 128k -> full row sums in-warp -> writes g_inv directly.
// SMEM: QH/QL (2x18432) + K double buffer (2x2x18432) = 110592 B.
// ============================================================================
#define S2_QH 0
#define S2_QL 18432
#define S2_KB 36864
#define SCORES2_SMEM 110592

__global__ __launch_bounds__(256, 1)
void scores2_kernel(const float* __restrict__ Q, const float* __restrict__ Kmat,
                    const int* __restrict__ mask, float* __restrict__ P,
                    float* __restrict__ inv)
{
    extern __shared__ __align__(16) char smem[];
    const uint32_t sb = smem_u32(smem);

    const int tid  = threadIdx.x;
    const int w    = tid >> 5;
    const int lane = tid & 31;
    const int bh   = blockIdx.y;
    const int b    = bh >> 4;
    const int h    = bh & 15;
    const int q0   = blockIdx.x * 128;

    // ---- load + split Q once ----
    const float* Qp = Q + (size_t)(b * S_ + q0) * D_ + h * HD_;
    #pragma unroll
    for (int i = 0; i < 8; i++) {
        int idx = tid + i * 256;
        int r = idx >> 4, c4 = idx & 15;
        uint2 hi, lo;
        split4(__ldg((const float4*)(Qp + (size_t)r * D_ + c4 * 4)), hi, lo);
        const uint32_t off = (uint32_t)(r * 144 + c4 * 8);
        *reinterpret_cast<uint2*>(smem + S2_QH + off) = hi;
        *reinterpret_cast<uint2*>(smem + S2_QL + off) = lo;
    }
    __syncthreads();

    // register-resident Q A-frags (held for the whole kernel)
    uint32_t qh[4][4], ql[4][4];
    {
        const uint32_t qa = sb + (uint32_t)((w * 16 + (lane & 15)) * 144 + (lane >> 4) * 16);
        #pragma unroll
        for (int ks = 0; ks < 4; ks++) {
            ldmat_x4(qh[ks], qa + S2_QH + ks * 32);
            ldmat_x4(ql[ks], qa + S2_QL + ks * 32);
        }
    }
    __syncthreads();

    const float* Kb = Kmat + (size_t)(b * S_) * D_ + h * HD_;
    const int frow = tid >> 4;       // 0..15 strided by 16 via i
    const int fc4  = tid & 15;

    float4 vk[8];
    #pragma unroll
    for (int i = 0; i < 8; i++)
        vk[i] = __ldg((const float4*)(Kb + (size_t)(frow + i * 16) * D_ + fc4 * 4));

    float s_lo = 0.f, s_hi = 0.f;
    const int rql = lane >> 2;                 // 0..7
    const int cql = (lane & 3) * 2;
    float* Pb = P + (size_t)bh * S_ * S_;
    const int rg = q0 + w * 16 + rql;          // global q row (and +8)

    for (int t = 0; t < 16; t++) {
        const uint32_t KHo = (uint32_t)(S2_KB + (t & 1) * 36864);
        const uint32_t KLo = KHo + 18432;

        // store K(t) split
        #pragma unroll
        for (int i = 0; i < 8; i++) {
            uint2 hi, lo;
            split4(vk[i], hi, lo);
            const uint32_t off = (uint32_t)((frow + i * 16) * 144 + fc4 * 8);
            *reinterpret_cast<uint2*>(smem + KHo + off) = hi;
            *reinterpret_cast<uint2*>(smem + KLo + off) = lo;
        }
        __syncthreads();

        // prefetch K(t+1)
        if (t < 15) {
            const float* Kp = Kb + (size_t)(t + 1) * 128 * D_;
            #pragma unroll
            for (int i = 0; i < 8; i++)
                vk[i] = __ldg((const float4*)(Kp + (size_t)(frow + i * 16) * D_ + fc4 * 4));
        }

        // scores MMA: 16 n-frags x 4 k-chunks x 3 terms
        float acc[16][4] = {};
        const uint32_t bB = sb + (uint32_t)((lane & 7) * 144 + ((lane >> 3) & 1) * 16);
        #pragma unroll
        for (int ks = 0; ks < 4; ks++) {
            #pragma unroll
            for (int nf = 0; nf < 16; nf++) {
                uint32_t kh[2], kl[2];
                const uint32_t ba = bB + (uint32_t)(nf * 1152 + ks * 32);
                ldmat_x2(kh, ba + KHo);
                ldmat_x2(kl, ba + KLo);
                mma16816(acc[nf], qh[ks], kh);
                mma16816(acc[nf], qh[ks], kl);
                mma16816(acc[nf], ql[ks], kh);
            }
        }

        // epilogue: mask + exp + rowsum + store P (unnormalized)
        const int k0g = t * 128;
        #pragma unroll
        for (int nf = 0; nf < 16; nf++) {
            const int c = k0g + nf * 8 + cql;
            const int2 m2 = *reinterpret_cast<const int2*>(&mask[b * S_ + c]);
            float e0 = m2.x ? __expf(acc[nf][0] * 0.125f) : 0.f;
            float e1 = m2.y ? __expf(acc[nf][1] * 0.125f) : 0.f;
            float e2 = m2.x ? __expf(acc[nf][2] * 0.125f) : 0.f;
            float e3 = m2.y ? __expf(acc[nf][3] * 0.125f) : 0.f;
            s_lo += e0 + e1;
            s_hi += e2 + e3;
            *reinterpret_cast<float2*>(&Pb[(size_t)rg * S_ + c])       = make_float2(e0, e1);
            *reinterpret_cast<float2*>(&Pb[(size_t)(rg + 8) * S_ + c]) = make_float2(e2, e3);
        }
    }

    // full row sums (within lane quad) -> 1/sum
    s_lo += __shfl_xor_sync(0xffffffffu, s_lo, 1);
    s_lo += __shfl_xor_sync(0xffffffffu, s_lo, 2);
    s_hi += __shfl_xor_sync(0xffffffffu, s_hi, 1);
    s_hi += __shfl_xor_sync(0xffffffffu, s_hi, 2);
    if ((lane & 3) == 0) {
        inv[(size_t)bh * S_ + rg]     = 1.0f / s_lo;
        inv[(size_t)bh * S_ + rg + 8] = 1.0f / s_hi;
    }
}

// ============================================================================
// av2: X = (P * inv) @ V ; P normalized in-place.
// P goes gmem -> registers (A-frag layout is per-lane float2s) -> normalize ->
// write back -> fp16x3 split. NO smem / ldmatrix for P at all.
// V 64k x 64hd tiles, double-buffered + reg-prefetched, trans ldmatrix B-frags.
// SMEM: V hi/lo x 2 buffers = 36864 B.
// ============================================================================
#define AV2_SMEM 36864

__global__ __launch_bounds__(256, 1)
void av2_kernel(float* __restrict__ P, const float* __restrict__ V,
                const float* __restrict__ inv, float* __restrict__ X)
{
    extern __shared__ __align__(16) char smem[];
    const uint32_t sb = smem_u32(smem);

    const int tid  = threadIdx.x;
    const int w    = tid >> 5;
    const int lane = tid & 31;
    const int bh   = blockIdx.y;
    const int b    = bh >> 4;
    const int h    = bh & 15;
    const int q0   = blockIdx.x * 128;

    const int rg = q0 + w * 16 + (lane >> 2);
    const float inv_lo = __ldg(&inv[(size_t)bh * S_ + rg]);
    const float inv_hi = __ldg(&inv[(size_t)bh * S_ + rg + 8]);

    float* Pb = P + (size_t)bh * S_ * S_;
    float* rp0 = Pb + (size_t)rg * S_;
    float* rp1 = Pb + (size_t)(rg + 8) * S_;
    const float* Vb = V + (size_t)b * S_ * D_ + h * HD_;

    const int vrow = tid >> 4;        // 0..15 (x4 via i)
    const int vc4  = tid & 15;

    float4 vv[4];
    #pragma unroll
    for (int i = 0; i < 4; i++)
        vv[i] = __ldg((const float4*)(Vb + (size_t)(vrow + i * 16) * D_ + vc4 * 4));

    float acc[8][4] = {};
    const int cql = (lane & 3) * 2;

    for (int t = 0; t < 32; t++) {
        const uint32_t VHo = (uint32_t)((t & 1) * 18432);
        const uint32_t VLo = VHo + 9216;

        // store V(t) split
        #pragma unroll
        for (int i = 0; i < 4; i++) {
            uint2 hi, lo;
            split4(vv[i], hi, lo);
            const uint32_t off = (uint32_t)((vrow + i * 16) * 144 + vc4 * 8);
            *reinterpret_cast<uint2*>(smem + VHo + off) = hi;
            *reinterpret_cast<uint2*>(smem + VLo + off) = lo;
        }
        __syncthreads();

        // prefetch V(t+1)
        if (t < 31) {
            const float* Vp = Vb + (size_t)(t + 1) * 64 * D_;
            #pragma unroll
            for (int i = 0; i < 4; i++)
                vv[i] = __ldg((const float4*)(Vp + (size_t)(vrow + i * 16) * D_ + vc4 * 4));
        }

        // P fragments straight from gmem: normalize, write back, split
        const int k0 = t * 64;
        uint32_t ah[4][4], al[4][4];
        #pragma unroll
        for (int ks = 0; ks < 4; ks++) {
            const int c = k0 + ks * 16 + cql;
            float2 p00 = *reinterpret_cast<const float2*>(rp0 + c);
            float2 p10 = *reinterpret_cast<const float2*>(rp1 + c);
            float2 p01 = *reinterpret_cast<const float2*>(rp0 + c + 8);
            float2 p11 = *reinterpret_cast<const float2*>(rp1 + c + 8);
            p00.x *= inv_lo; p00.y *= inv_lo;
            p01.x *= inv_lo; p01.y *= inv_lo;
            p10.x *= inv_hi; p10.y *= inv_hi;
            p11.x *= inv_hi; p11.y *= inv_hi;
            *reinterpret_cast<float2*>(rp0 + c)     = p00;
            *reinterpret_cast<float2*>(rp1 + c)     = p10;
            *reinterpret_cast<float2*>(rp0 + c + 8) = p01;
            *reinterpret_cast<float2*>(rp1 + c + 8) = p11;
            split2(p00, ah[ks][0], al[ks][0]);
            split2(p10, ah[ks][1], al[ks][1]);
            split2(p01, ah[ks][2], al[ks][2]);
            split2(p11, ah[ks][3], al[ks][3]);
        }

        // B-frags from V (trans) + MMA
        const uint32_t vB = sb + (uint32_t)((lane & 15) * 144);
        #pragma unroll
        for (int ks = 0; ks < 4; ks++) {
            #pragma unroll
            for (int nf = 0; nf < 8; nf++) {
                uint32_t vh[2], vl[2];
                const uint32_t ba = vB + (uint32_t)(ks * 16 * 144 + nf * 16);
                ldmat_x2_trans(vh, ba + VHo);
                ldmat_x2_trans(vl, ba + VLo);
                mma16816(acc[nf], ah[ks], vh);
                mma16816(acc[nf], ah[ks], vl);
                mma16816(acc[nf], al[ks], vh);
            }
        }
        __syncthreads();
    }

    // X epilogue: [B, S, D]
    #pragma unroll
    for (int nf = 0; nf < 8; nf++) {
        const int c = h * HD_ + nf * 8 + cql;
        *reinterpret_cast<float2*>(&X[(size_t)(b * S_ + rg) * D_ + c]) =
            make_float2(acc[nf][0], acc[nf][1]);
        *reinterpret_cast<float2*>(&X[(size_t)(b * S_ + rg + 8) * D_ + c]) =
            make_float2(acc[nf][2], acc[nf][3]);
    }
}

// ---------------------------------------------------------------------------
extern "C" void kernel_launch(void* const* d_in, const int* in_sizes, int n_in,
                              void* d_out, int out_size)
{
    (void)in_sizes; (void)n_in; (void)out_size;

    const float* query = (const float*)d_in[0];
    const float* key_  = (const float*)d_in[1];
    const float* value = (const float*)d_in[2];
    const int*   mask  = (const int*)d_in[3];
    const float* Wq    = (const float*)d_in[4];
    const float* bq    = (const float*)d_in[5];
    const float* Wk    = (const float*)d_in[6];
    const float* bk    = (const float*)d_in[7];
    const float* Wv    = (const float*)d_in[8];
    const float* bv    = (const float*)d_in[9];
    const float* Wo    = (const float*)d_in[10];
    const float* bo    = (const float*)d_in[11];

    float* xout = (float*)d_out;                 // [B,S,D]
    float* pout = xout + (size_t)B_ * S_ * D_;   // [B,H,S,S]

    void *pQ, *pK, *pV, *pX, *pI;
    cudaGetSymbolAddress(&pQ, g_Q);
    cudaGetSymbolAddress(&pK, g_K);
    cudaGetSymbolAddress(&pV, g_V);
    cudaGetSymbolAddress(&pX, g_X);
    cudaGetSymbolAddress(&pI, g_inv);

    cudaFuncSetAttribute(proj_mma_kernel,
                         cudaFuncAttributeMaxDynamicSharedMemorySize, PROJ_SMEM);
    cudaFuncSetAttribute(scores2_kernel,
                         cudaFuncAttributeMaxDynamicSharedMemorySize, SCORES2_SMEM);
    cudaFuncSetAttribute(av2_kernel,
                         cudaFuncAttributeMaxDynamicSharedMemorySize, AV2_SMEM);

    const dim3 gproj(D_ / 128, (B_ * S_) / 128);   // (8, 64)

    proj_mma_kernel<<<gproj, 256, PROJ_SMEM>>>(query, Wq, bq, (float*)pQ);
    proj_mma_kernel<<<gproj, 256, PROJ_SMEM>>>(key_,  Wk, bk, (float*)pK);
    proj_mma_kernel<<<gproj, 256, PROJ_SMEM>>>(value, Wv, bv, (float*)pV);

    scores2_kernel<<<dim3(S_ / 128, BH_), 256, SCORES2_SMEM>>>(
        (const float*)pQ, (const float*)pK, mask, pout, (float*)pI);

    av2_kernel<<<dim3(S_ / 128, BH_), 256, AV2_SMEM>>>(
        pout, (const float*)pV, (const float*)pI, (float*)pX);

    proj_mma_kernel<<<gproj, 256, PROJ_SMEM>>>((const float*)pX, Wo, bo, xout);
}